// round 2
// baseline (speedup 1.0000x reference)
#include <cuda_runtime.h>
#include <math.h>
#include <stdint.h>

#define TT 2048
#define HH 1024
#define DD 512
#define EE 64
#define TOPK 2

// ---------------- scratch (device globals; no allocation allowed) ----------------
__device__ int   g_topk_i[TT * TOPK];
__device__ float g_topk_w[TT * TOPK];
__device__ int   g_counts[EE];
__device__ int   g_list[EE * TT];             // pairid = t*2+k entries, grouped by expert
__device__ float g_act[TT * TOPK * DD];        // 8 MB activation scratch
__device__ float g_usage_partial[64 * EE];     // [router_block][expert]
__device__ int2  g_tiles[256];                 // {expert, m0}; -1-padded

// ---------------- zero out + counts ----------------
__global__ void k_zero(float* __restrict__ out) {
    int i = blockIdx.x * blockDim.x + threadIdx.x;
    int stride = gridDim.x * blockDim.x;
    for (int j = i; j < TT * HH; j += stride) out[j] = 0.f;
    if (i < EE) g_counts[i] = 0;
}

// ---------------- router: logits GEMM + top2 + softmax stats ----------------
// one block per 32 tokens; 256 threads
__global__ __launch_bounds__(256) void k_router(const float* __restrict__ x,
                                                const float* __restrict__ gate) {
    __shared__ float Xs[32][33];
    __shared__ float Gs[32][68];
    __shared__ float Ls[32][65];
    __shared__ float sM[32], sInv[32];

    const int t0 = blockIdx.x * 32;
    const int tid = threadIdx.x;
    const int tx = tid & 15, ty = tid >> 4;

    float acc[2][4];
#pragma unroll
    for (int i = 0; i < 2; i++)
#pragma unroll
        for (int j = 0; j < 4; j++) acc[i][j] = 0.f;

    for (int k0 = 0; k0 < HH; k0 += 32) {
        // X tile: 32 tokens x 32 k
        {
            int m = tid >> 3, k4 = (tid & 7) * 4;
            float4 v = *(const float4*)(x + (size_t)(t0 + m) * HH + k0 + k4);
            Xs[m][k4 + 0] = v.x; Xs[m][k4 + 1] = v.y;
            Xs[m][k4 + 2] = v.z; Xs[m][k4 + 3] = v.w;
        }
        // gate tile: 32 k x 64 experts (gate is [H][E] row-major)
        {
            int k = tid >> 4, j4 = (tid & 15) * 4;
#pragma unroll
            for (int r = 0; r < 2; r++) {
                float4 v = *(const float4*)(gate + (size_t)(k0 + k + r * 16) * EE + j4);
                *(float4*)&Gs[k + r * 16][j4] = v;
            }
        }
        __syncthreads();
#pragma unroll
        for (int kk = 0; kk < 32; kk++) {
            float a0 = Xs[ty * 2 + 0][kk];
            float a1 = Xs[ty * 2 + 1][kk];
            float4 b = *(float4*)&Gs[kk][tx * 4];
            acc[0][0] += a0 * b.x; acc[0][1] += a0 * b.y; acc[0][2] += a0 * b.z; acc[0][3] += a0 * b.w;
            acc[1][0] += a1 * b.x; acc[1][1] += a1 * b.y; acc[1][2] += a1 * b.z; acc[1][3] += a1 * b.w;
        }
        __syncthreads();
    }
    // logits -> smem
#pragma unroll
    for (int mi = 0; mi < 2; mi++)
#pragma unroll
        for (int ni = 0; ni < 4; ni++)
            Ls[ty * 2 + mi][tx * 4 + ni] = acc[mi][ni];
    __syncthreads();

    // per-token top2 + softmax denominator (thread r handles token r)
    if (tid < 32) {
        int t = t0 + tid;
        float m1 = -1e30f, m2 = -1e30f;
        int i1 = -1, i2 = -1;
        for (int e = 0; e < EE; e++) {
            float l = Ls[tid][e];
            if (l > m1) { m2 = m1; i2 = i1; m1 = l; i1 = e; }
            else if (l > m2) { m2 = l; i2 = e; }
        }
        float den = 0.f;
        for (int e = 0; e < EE; e++) den += __expf(Ls[tid][e] - m1);
        sM[tid] = m1; sInv[tid] = 1.f / den;
        float e2 = __expf(m2 - m1);
        float s = 1.f + e2;
        g_topk_i[t * 2 + 0] = i1;
        g_topk_i[t * 2 + 1] = i2;
        g_topk_w[t * 2 + 0] = 1.f / s;
        g_topk_w[t * 2 + 1] = e2 / s;
    }
    __syncthreads();

    // deterministic expert-usage partial for this block (thread e handles expert e)
    if (tid < EE) {
        float s = 0.f;
        for (int r = 0; r < 32; r++)
            s += __expf(Ls[r][tid] - sM[r]) * sInv[r];
        g_usage_partial[blockIdx.x * EE + tid] = s;
    }
}

// ---------------- lb loss ----------------
__global__ void k_lb(float* __restrict__ out_lb) {
    __shared__ float red[64];
    int e = threadIdx.x;
    float s = 0.f;
    for (int b = 0; b < 64; b++) s += g_usage_partial[b * EE + e];
    float u = s / (float)TT;
    red[e] = u * u;
    __syncthreads();
    for (int off = 32; off > 0; off >>= 1) {
        if (e < off) red[e] += red[e + off];
        __syncthreads();
    }
    if (e == 0) *out_lb = (float)EE * red[0];
}

// ---------------- build per-expert token lists ----------------
__global__ void k_build_lists() {
    int t = blockIdx.x * blockDim.x + threadIdx.x;
    if (t < TT) {
#pragma unroll
        for (int k = 0; k < TOPK; k++) {
            int e = g_topk_i[t * 2 + k];
            int pos = atomicAdd(&g_counts[e], 1);
            g_list[e * TT + pos] = t * 2 + k;
        }
    }
}

// ---------------- build tile list (fixed grid for graph capture) ----------------
__global__ void k_build_tiles() {
    int tid = threadIdx.x;
    if (tid < 256) g_tiles[tid] = make_int2(-1, 0);
    __syncthreads();
    if (tid == 0) {
        int n = 0;
        for (int e = 0; e < EE; e++) {
            int c = g_counts[e];
            for (int m0 = 0; m0 < c; m0 += 32) g_tiles[n++] = make_int2(e, m0);
        }
    }
}

// ---------------- GEMM A: act = silu(x@w1) * (x@w3), grouped per expert ----------------
// grid (256 tiles, 8 n-tiles of 64), 256 threads
__global__ __launch_bounds__(256) void k_gemmA(const float* __restrict__ x,
                                               const float* __restrict__ w1,
                                               const float* __restrict__ w3) {
    int2 tile = g_tiles[blockIdx.x];
    int e = tile.x;
    if (e < 0) return;
    int m0 = tile.y;
    int cnt = g_counts[e];
    int n0 = blockIdx.y * 64;

    __shared__ float Xs[32][33];
    __shared__ float W1s[32][68];
    __shared__ float W3s[32][68];
    __shared__ int sPair[32];

    const int tid = threadIdx.x;
    if (tid < 32) {
        int idx = m0 + tid;
        sPair[tid] = (idx < cnt) ? g_list[e * TT + idx] : -1;
    }
    __syncthreads();

    const int tx = tid & 15, ty = tid >> 4;
    const float* w1e = w1 + (size_t)e * HH * DD;
    const float* w3e = w3 + (size_t)e * HH * DD;

    float acc1[2][4], acc3[2][4];
#pragma unroll
    for (int i = 0; i < 2; i++)
#pragma unroll
        for (int j = 0; j < 4; j++) { acc1[i][j] = 0.f; acc3[i][j] = 0.f; }

    for (int k0 = 0; k0 < HH; k0 += 32) {
        {
            int m = tid >> 3, k4 = (tid & 7) * 4;
            int p = sPair[m];
            float4 v = make_float4(0.f, 0.f, 0.f, 0.f);
            if (p >= 0) v = *(const float4*)(x + (size_t)(p >> 1) * HH + k0 + k4);
            Xs[m][k4 + 0] = v.x; Xs[m][k4 + 1] = v.y;
            Xs[m][k4 + 2] = v.z; Xs[m][k4 + 3] = v.w;
        }
        {
            int k = tid >> 4, j4 = (tid & 15) * 4;
#pragma unroll
            for (int r = 0; r < 2; r++) {
                int kk_ = k + r * 16;
                *(float4*)&W1s[kk_][j4] = *(const float4*)(w1e + (size_t)(k0 + kk_) * DD + n0 + j4);
                *(float4*)&W3s[kk_][j4] = *(const float4*)(w3e + (size_t)(k0 + kk_) * DD + n0 + j4);
            }
        }
        __syncthreads();
#pragma unroll
        for (int kk = 0; kk < 32; kk++) {
            float a0 = Xs[ty * 2 + 0][kk];
            float a1 = Xs[ty * 2 + 1][kk];
            float4 b1 = *(float4*)&W1s[kk][tx * 4];
            float4 b3 = *(float4*)&W3s[kk][tx * 4];
            acc1[0][0] += a0 * b1.x; acc1[0][1] += a0 * b1.y; acc1[0][2] += a0 * b1.z; acc1[0][3] += a0 * b1.w;
            acc1[1][0] += a1 * b1.x; acc1[1][1] += a1 * b1.y; acc1[1][2] += a1 * b1.z; acc1[1][3] += a1 * b1.w;
            acc3[0][0] += a0 * b3.x; acc3[0][1] += a0 * b3.y; acc3[0][2] += a0 * b3.z; acc3[0][3] += a0 * b3.w;
            acc3[1][0] += a1 * b3.x; acc3[1][1] += a1 * b3.y; acc3[1][2] += a1 * b3.z; acc3[1][3] += a1 * b3.w;
        }
        __syncthreads();
    }

#pragma unroll
    for (int mi = 0; mi < 2; mi++) {
        int m = ty * 2 + mi;
        int p = sPair[m];
        if (p >= 0) {
            float4 o;
            { float h = acc1[mi][0], g = acc3[mi][0]; o.x = h * g / (1.f + __expf(-h)); }
            { float h = acc1[mi][1], g = acc3[mi][1]; o.y = h * g / (1.f + __expf(-h)); }
            { float h = acc1[mi][2], g = acc3[mi][2]; o.z = h * g / (1.f + __expf(-h)); }
            { float h = acc1[mi][3], g = acc3[mi][3]; o.w = h * g / (1.f + __expf(-h)); }
            *(float4*)(g_act + (size_t)p * DD + n0 + tx * 4) = o;
        }
    }
}

// ---------------- GEMM B: out += cw * (act @ w2), grouped per expert ----------------
// grid (256 tiles, 16 n-tiles of 64), 256 threads
__global__ __launch_bounds__(256) void k_gemmB(const float* __restrict__ w2,
                                               float* __restrict__ out) {
    int2 tile = g_tiles[blockIdx.x];
    int e = tile.x;
    if (e < 0) return;
    int m0 = tile.y;
    int cnt = g_counts[e];
    int n0 = blockIdx.y * 64;

    __shared__ float As[32][33];
    __shared__ float Bs[32][68];
    __shared__ int sPair[32];
    __shared__ float sW[32];

    const int tid = threadIdx.x;
    if (tid < 32) {
        int idx = m0 + tid;
        int p = (idx < cnt) ? g_list[e * TT + idx] : -1;
        sPair[tid] = p;
        sW[tid] = (p >= 0) ? g_topk_w[p] : 0.f;
    }
    __syncthreads();

    const int tx = tid & 15, ty = tid >> 4;
    const float* w2e = w2 + (size_t)e * DD * HH;

    float acc[2][4];
#pragma unroll
    for (int i = 0; i < 2; i++)
#pragma unroll
        for (int j = 0; j < 4; j++) acc[i][j] = 0.f;

    for (int k0 = 0; k0 < DD; k0 += 32) {
        {
            int m = tid >> 3, k4 = (tid & 7) * 4;
            int p = sPair[m];
            float4 v = make_float4(0.f, 0.f, 0.f, 0.f);
            if (p >= 0) v = *(const float4*)(g_act + (size_t)p * DD + k0 + k4);
            As[m][k4 + 0] = v.x; As[m][k4 + 1] = v.y;
            As[m][k4 + 2] = v.z; As[m][k4 + 3] = v.w;
        }
        {
            int k = tid >> 4, j4 = (tid & 15) * 4;
#pragma unroll
            for (int r = 0; r < 2; r++) {
                int kk_ = k + r * 16;
                *(float4*)&Bs[kk_][j4] = *(const float4*)(w2e + (size_t)(k0 + kk_) * HH + n0 + j4);
            }
        }
        __syncthreads();
#pragma unroll
        for (int kk = 0; kk < 32; kk++) {
            float a0 = As[ty * 2 + 0][kk];
            float a1 = As[ty * 2 + 1][kk];
            float4 b = *(float4*)&Bs[kk][tx * 4];
            acc[0][0] += a0 * b.x; acc[0][1] += a0 * b.y; acc[0][2] += a0 * b.z; acc[0][3] += a0 * b.w;
            acc[1][0] += a1 * b.x; acc[1][1] += a1 * b.y; acc[1][2] += a1 * b.z; acc[1][3] += a1 * b.w;
        }
        __syncthreads();
    }

#pragma unroll
    for (int mi = 0; mi < 2; mi++) {
        int m = ty * 2 + mi;
        int p = sPair[m];
        if (p >= 0) {
            int t = p >> 1;
            float wgt = sW[m];
            float* dst = out + (size_t)t * HH + n0 + tx * 4;
            atomicAdd(dst + 0, acc[mi][0] * wgt);
            atomicAdd(dst + 1, acc[mi][1] * wgt);
            atomicAdd(dst + 2, acc[mi][2] * wgt);
            atomicAdd(dst + 3, acc[mi][3] * wgt);
        }
    }
}

// ---------------- launch ----------------
extern "C" void kernel_launch(void* const* d_in, const int* in_sizes, int n_in,
                              void* d_out, int out_size) {
    const float* x    = (const float*)d_in[0];
    const float* w1   = (const float*)d_in[1];
    const float* w3   = (const float*)d_in[2];
    const float* w2   = (const float*)d_in[3];
    const float* gate = (const float*)d_in[4];
    float* out = (float*)d_out;

    k_zero<<<512, 256>>>(out);
    k_router<<<64, 256>>>(x, gate);
    k_build_lists<<<8, 256>>>();
    k_build_tiles<<<1, 256>>>();
    k_gemmA<<<dim3(256, 8), 256>>>(x, w1, w3);
    k_gemmB<<<dim3(256, 16), 256>>>(w2, out);
    if (out_size > TT * HH) {
        k_lb<<<1, 64>>>(out + TT * HH);
    }
}